// round 1
// baseline (speedup 1.0000x reference)
#include <cuda_runtime.h>
#include <math.h>

#define BB   16
#define LL   4096
#define DD   512
#define LP1  4097
#define D4   128        // D / 4 float4 per row
#define CH   64         // l-chunk per recurrence thread

// Scratch (no allocations allowed): per-d coefficient + emb table (8 MB).
__device__ float g_c[DD];
__device__ float g_emb[LL * DD];

// ---------------------------------------------------------------------------
// Kernel 0: c[d] = 100^(-(d - d%2)/512) + (pi/2)*(d%2), computed in double
// then rounded to f32 to match the reference's f32 coefficient closely.
// ---------------------------------------------------------------------------
__global__ void compute_c_kernel() {
    int d = threadIdx.x;
    double e = (double)(d & ~1) / (double)DD;
    float freq = (float)pow(100.0, -e);
    float phase = (d & 1) ? 1.57079632679489662f : 0.0f;
    g_c[d] = freq + phase;
}

// ---------------------------------------------------------------------------
// Kernel 1: emb[l][d] = sin(l * c[d]) via angle-addition recurrence.
// One thread per d, one block per CH consecutive l values.
// 2M table entries cost only 64*512 = 32K sincosf anchors + 4 FMA/entry.
// Writes are coalesced: lane d, lane d+1 -> adjacent floats.
// ---------------------------------------------------------------------------
__global__ void compute_emb_kernel() {
    int d  = threadIdx.x;           // 0..511
    int l0 = blockIdx.x * CH;       // 64 blocks
    float c = g_c[d];

    float s, cs, sd, cd;
    sincosf((float)l0 * c, &s, &cs);   // exact anchor at chunk start
    sincosf(c, &sd, &cd);              // step rotation

    float* p = &g_emb[l0 * DD + d];
#pragma unroll
    for (int k = 0; k < CH; k++) {
        p[k * DD] = s;
        float ns = fmaf(s,  cd, cs * sd);
        float nc = fmaf(cs, cd, -(s * sd));
        s = ns; cs = nc;
    }
}

// ---------------------------------------------------------------------------
// Kernel 2: stream out[b,l,:] = tokens+emb (l<len) | cls (l==len) | 0 (else).
// 512 threads / block, 4 rows / block, float4 lanes. Token loads are skipped
// entirely for invalid rows (saves ~half the token read traffic).
// ---------------------------------------------------------------------------
__global__ void __launch_bounds__(512)
stream_kernel(const float4* __restrict__ tok,
              const int*    __restrict__ lengths,
              const float4* __restrict__ cls,
              float4*       __restrict__ out)
{
    int t   = threadIdx.x;
    int row = blockIdx.x * 4 + (t >> 7);       // 0 .. B*(L+1)-1
    int d4  = t & (D4 - 1);                     // 0..127

    int b = row / LP1;
    int l = row - b * LP1;
    int len = __ldg(&lengths[b]);

    float4 v;
    if (l < len) {
        float4 tk = tok[(size_t)(b * LL + l) * D4 + d4];
        float4 em = reinterpret_cast<const float4*>(g_emb)[l * D4 + d4];
        v.x = tk.x + em.x;
        v.y = tk.y + em.y;
        v.z = tk.z + em.z;
        v.w = tk.w + em.w;
    } else if (l == len) {
        v = cls[d4];
    } else {
        v = make_float4(0.f, 0.f, 0.f, 0.f);
    }
    out[(size_t)row * D4 + d4] = v;
}

// ---------------------------------------------------------------------------
extern "C" void kernel_launch(void* const* d_in, const int* in_sizes, int n_in,
                              void* d_out, int out_size)
{
    const float4* tok     = (const float4*)d_in[0];   // tokens  [B,L,D] f32
    const int*    lengths = (const int*)   d_in[1];   // lengths [B]    i32
    const float4* cls     = (const float4*)d_in[2];   // cls     [D]    f32
    float4*       out     = (float4*)d_out;           // [B,L+1,D] f32

    compute_c_kernel<<<1, DD>>>();
    compute_emb_kernel<<<LL / CH, DD>>>();

    int n_rows = BB * LP1;                  // 65552
    stream_kernel<<<n_rows / 4, 512>>>(tok, lengths, cls, out);
}

// round 2
// speedup vs baseline: 1.3643x; 1.3643x over previous
#include <cuda_runtime.h>
#include <math.h>

#define BB   16
#define LL   4096
#define DD   512
#define LP1  4097
#define D4   128        // D / 4 float4 per row
#define CH   32         // l-chunk per recurrence thread

// Scratch (no allocations allowed): emb table (8 MB).
__device__ float g_emb[LL * DD];

// ---------------------------------------------------------------------------
// Coefficient c[d] = 100^(-(d - d%2)/512) + (pi/2)*(d%2), computed exactly as
// r^(d>>1) with r = 100^(-1/256) (double constant, binary exponentiation —
// pure DMUL, no software pow). Relative error ~2.5e-10, below f32 ulp.
// ---------------------------------------------------------------------------
__device__ __forceinline__ float coef(int d) {
    const double R = 0.982171889188039;   // 100^(-1/256)
    double f = 1.0, p = R;
    int k = d >> 1;                        // 0..255
#pragma unroll
    for (int i = 0; i < 8; i++) {
        if (k & 1) f *= p;
        p *= p;
        k >>= 1;
    }
    return (float)f + ((d & 1) ? 1.57079632679489662f : 0.0f);
}

// ---------------------------------------------------------------------------
// Kernel 1: emb[l][d] = sin(l * c[d]) via angle-addition recurrence.
// One thread per d, one block per CH consecutive l values (128 blocks).
// Anchored by sincosf at each chunk start; 4 FMA per table entry after that.
// Writes coalesced: adjacent lanes -> adjacent floats.
// ---------------------------------------------------------------------------
__global__ void __launch_bounds__(DD)
compute_emb_kernel() {
    int d  = threadIdx.x;           // 0..511
    int l0 = blockIdx.x * CH;       // 128 blocks
    float c = coef(d);

    float s, cs, sd, cd;
    sincosf((float)l0 * c, &s, &cs);   // exact anchor at chunk start
    sincosf(c, &sd, &cd);              // step rotation

    float* p = &g_emb[l0 * DD + d];
#pragma unroll
    for (int k = 0; k < CH; k++) {
        p[k * DD] = s;
        float ns = fmaf(s,  cd, cs * sd);
        float nc = fmaf(cs, cd, -(s * sd));
        s = ns; cs = nc;
    }
}

// ---------------------------------------------------------------------------
// Kernel 2: stream out[b,l,:] = tokens+emb (l<len) | cls (l==len) | 0 (else).
// 512 threads / block, 4 rows / block, float4 lanes. Token loads skipped
// entirely for invalid rows. emb table (8 MB) stays L2-resident across the
// 16 batch passes, so DRAM traffic ~ 134 MB write + ~67 MB token read.
// ---------------------------------------------------------------------------
__global__ void __launch_bounds__(512)
stream_kernel(const float4* __restrict__ tok,
              const int*    __restrict__ lengths,
              const float4* __restrict__ cls,
              float4*       __restrict__ out)
{
    int t   = threadIdx.x;
    int row = blockIdx.x * 4 + (t >> 7);       // 0 .. B*(L+1)-1
    int d4  = t & (D4 - 1);                     // 0..127

    int b = row / LP1;
    int l = row - b * LP1;
    int len = __ldg(&lengths[b]);

    float4 v;
    if (l < len) {
        float4 tk = tok[(size_t)(b * LL + l) * D4 + d4];
        float4 em = reinterpret_cast<const float4*>(g_emb)[l * D4 + d4];
        v.x = tk.x + em.x;
        v.y = tk.y + em.y;
        v.z = tk.z + em.z;
        v.w = tk.w + em.w;
    } else if (l == len) {
        v = cls[d4];
    } else {
        v = make_float4(0.f, 0.f, 0.f, 0.f);
    }
    out[(size_t)row * D4 + d4] = v;
}

// ---------------------------------------------------------------------------
extern "C" void kernel_launch(void* const* d_in, const int* in_sizes, int n_in,
                              void* d_out, int out_size)
{
    const float4* tok     = (const float4*)d_in[0];   // tokens  [B,L,D] f32
    const int*    lengths = (const int*)   d_in[1];   // lengths [B]    i32
    const float4* cls     = (const float4*)d_in[2];   // cls     [D]    f32
    float4*       out     = (float4*)d_out;           // [B,L+1,D] f32

    compute_emb_kernel<<<LL / CH, DD>>>();

    int n_rows = BB * LP1;                  // 65552
    stream_kernel<<<n_rows / 4, 512>>>(tok, lengths, cls, out);
}